// round 2
// baseline (speedup 1.0000x reference)
#include <cuda_runtime.h>
#include <math.h>

// Problem constants
#define RC_    4        // R*CH
#define NN_    20000
#define EE_    100000
#define CC_    256
#define MTOT_  80000    // R*CH*N

// Scratch (static device globals; no allocation at runtime)
__device__ float g_xl[MTOT_ * CC_];     // x @ lin_W + lin_b
__device__ float g_sums[MTOT_ * CC_];   // scatter-add accumulator
__device__ float g_cnt[NN_];
__device__ float g_inv[NN_];
__device__ int   g_is64;                // 1 if edge_index is int64, 0 if int32

// ---------------------------------------------------------------------------
// Detect edge_index dtype: int64 little-endian with values < 2^31 has zero
// high words at all odd int32 positions; genuine int32 data has random node
// ids there. Single block, deterministic.
// ---------------------------------------------------------------------------
__global__ void detect_kernel(const int* __restrict__ ei32) {
    __shared__ int any_nonzero;
    if (threadIdx.x == 0) any_nonzero = 0;
    __syncthreads();
    if (ei32[2 * threadIdx.x + 1] != 0) atomicOr(&any_nonzero, 1);
    __syncthreads();
    if (threadIdx.x == 0) g_is64 = (any_nonzero == 0) ? 1 : 0;
}

__device__ __forceinline__ int load_idx(const int* ei32, int pos) {
    int v = g_is64 ? ei32[2 * pos] : ei32[pos];
    return min(max(v, 0), NN_ - 1);
}

// ---------------------------------------------------------------------------
// Zero the accumulator + counts. 20000 blocks x 256 thr = 5.12M float4.
// ---------------------------------------------------------------------------
__global__ void zero_kernel() {
    int idx = blockIdx.x * 256 + threadIdx.x;
    ((float4*)g_sums)[idx] = make_float4(0.f, 0.f, 0.f, 0.f);
    if (idx < NN_) g_cnt[idx] = 0.f;
}

// ---------------------------------------------------------------------------
// Degree count over destinations
// ---------------------------------------------------------------------------
__global__ void count_kernel(const int* __restrict__ ei32) {
    int e = blockIdx.x * 256 + threadIdx.x;
    if (e < EE_) atomicAdd(&g_cnt[load_idx(ei32, EE_ + e)], 1.0f);
}

__global__ void inv_kernel() {
    int n = blockIdx.x * 256 + threadIdx.x;
    if (n < NN_) g_inv[n] = 1.0f / fmaxf(g_cnt[n], 1.0f);
}

// ---------------------------------------------------------------------------
// SGEMM 1: g_xl = x @ lin_W + lin_b   (M=80000, K=256, N=256)
// BM=BN=128, BK=16, 256 threads, 8x8 per thread.
// ---------------------------------------------------------------------------
#define BM 128
#define BN 128
#define BK 16

__global__ __launch_bounds__(256) void gemm_xl_kernel(
    const float* __restrict__ A,     // x (80000 x 256)
    const float* __restrict__ B,     // lin_W (256 x 256)
    const float* __restrict__ bias)  // lin_b
{
    __shared__ float As[BK][BM + 4];   // transposed, padded (row stride 528B, 16B-aligned)
    __shared__ float Bs[BK][BN];

    const int bx = blockIdx.x;   // N tile (0..1)
    const int by = blockIdx.y;   // M tile (0..624)
    const int tid = threadIdx.x;
    const int tx = tid & 15;
    const int ty = tid >> 4;

    float acc[8][8];
#pragma unroll
    for (int i = 0; i < 8; i++)
#pragma unroll
        for (int j = 0; j < 8; j++) acc[i][j] = 0.f;

    const float* Ab = A + (size_t)by * BM * CC_;
    const float* Bb = B + bx * BN;

    for (int k0 = 0; k0 < CC_; k0 += BK) {
#pragma unroll
        for (int i = 0; i < 2; i++) {
            int idx = tid * 2 + i;        // 0..511
            int r   = idx >> 2;           // 0..127
            int c4  = (idx & 3) * 4;      // 0,4,8,12
            float4 v = *(const float4*)(Ab + r * CC_ + k0 + c4);
            As[c4 + 0][r] = v.x; As[c4 + 1][r] = v.y;
            As[c4 + 2][r] = v.z; As[c4 + 3][r] = v.w;
        }
#pragma unroll
        for (int i = 0; i < 2; i++) {
            int idx = tid * 2 + i;
            int r   = idx >> 5;           // 0..15
            int c4  = (idx & 31) * 4;     // 0..124
            *(float4*)&Bs[r][c4] = *(const float4*)(Bb + (k0 + r) * CC_ + c4);
        }
        __syncthreads();

#pragma unroll
        for (int k = 0; k < BK; k++) {
            float a[8], b[8];
            *(float4*)&a[0] = *(const float4*)&As[k][ty * 8];
            *(float4*)&a[4] = *(const float4*)&As[k][ty * 8 + 4];
            *(float4*)&b[0] = *(const float4*)&Bs[k][tx * 8];
            *(float4*)&b[4] = *(const float4*)&Bs[k][tx * 8 + 4];
#pragma unroll
            for (int i = 0; i < 8; i++)
#pragma unroll
                for (int j = 0; j < 8; j++) acc[i][j] += a[i] * b[j];
        }
        __syncthreads();
    }

#pragma unroll
    for (int i = 0; i < 8; i++) {
        int row = by * BM + ty * 8 + i;
        int col = bx * BN + tx * 8;
#pragma unroll
        for (int j = 0; j < 8; j += 4) {
            float4 v;
            v.x = acc[i][j + 0] + bias[col + j + 0];
            v.y = acc[i][j + 1] + bias[col + j + 1];
            v.z = acc[i][j + 2] + bias[col + j + 2];
            v.w = acc[i][j + 3] + bias[col + j + 3];
            *(float4*)&g_xl[(size_t)row * CC_ + col + j] = v;
        }
    }
}

// ---------------------------------------------------------------------------
// Message + scatter: one block per edge, thread c = channel.
// Bond-encoder emb recomputed per edge (shared across the 4 (r,ch) slices);
// exact-erf GELU; atomicAdd scatter into g_sums.
// ---------------------------------------------------------------------------
__global__ __launch_bounds__(256) void msg_kernel(
    const float* __restrict__ edge_attr,    // (E,16)
    const float* __restrict__ bond_W,       // (16,256)
    const float* __restrict__ bond_b,       // (256)
    const float* __restrict__ edge_weight,  // (RC, E)
    const int* __restrict__ ei32)           // (2, E) int32 or int64
{
    const int e = blockIdx.x;
    const int c = threadIdx.x;

    __shared__ float ea[16];
    if (c < 16) ea[c] = edge_attr[e * 16 + c];
    __syncthreads();

    float emb = bond_b[c];
#pragma unroll
    for (int d = 0; d < 16; d++) emb += ea[d] * bond_W[d * CC_ + c];

    const int src = load_idx(ei32, e);
    const int dst = load_idx(ei32, EE_ + e);

#pragma unroll
    for (int rc = 0; rc < RC_; rc++) {
        float w = edge_weight[rc * EE_ + e];
        float v = g_xl[(size_t)(rc * NN_ + src) * CC_ + c] + emb;
        float g = 0.5f * v * (1.0f + erff(v * 0.70710678118654752f)) * w;
        atomicAdd(&g_sums[(size_t)(rc * NN_ + dst) * CC_ + c], g);
    }
}

// ---------------------------------------------------------------------------
// SGEMM 2 (fused epilogue GEMM, K=512):
//   out = (g_sums * inv_cnt) @ linl_W + x @ linr_W + linl_b
// ---------------------------------------------------------------------------
__global__ __launch_bounds__(256) void gemm_out_kernel(
    const float* __restrict__ X,       // x (80000 x 256)
    const float* __restrict__ linlW,   // (256 x 256)
    const float* __restrict__ linlb,   // (256)
    const float* __restrict__ linrW,   // (256 x 256)
    float* __restrict__ out)
{
    __shared__ float As[BK][BM + 4];
    __shared__ float Bs[BK][BN];

    const int bx = blockIdx.x;
    const int by = blockIdx.y;
    const int tid = threadIdx.x;
    const int tx = tid & 15;
    const int ty = tid >> 4;

    float acc[8][8];
#pragma unroll
    for (int i = 0; i < 8; i++)
#pragma unroll
        for (int j = 0; j < 8; j++) acc[i][j] = 0.f;

    for (int k0 = 0; k0 < 2 * CC_; k0 += BK) {
        const bool first = (k0 < CC_);
        const int  kk    = first ? k0 : (k0 - CC_);
#pragma unroll
        for (int i = 0; i < 2; i++) {
            int idx = tid * 2 + i;
            int r   = idx >> 2;
            int c4  = (idx & 3) * 4;
            int row = by * BM + r;
            float4 v;
            if (first) {
                v = *(const float4*)&g_sums[(size_t)row * CC_ + kk + c4];
                float s = g_inv[row % NN_];
                v.x *= s; v.y *= s; v.z *= s; v.w *= s;
            } else {
                v = *(const float4*)(X + (size_t)row * CC_ + kk + c4);
            }
            As[c4 + 0][r] = v.x; As[c4 + 1][r] = v.y;
            As[c4 + 2][r] = v.z; As[c4 + 3][r] = v.w;
        }
        const float* Bp = (first ? linlW : linrW) + kk * CC_ + bx * BN;
#pragma unroll
        for (int i = 0; i < 2; i++) {
            int idx = tid * 2 + i;
            int r   = idx >> 5;
            int c4  = (idx & 31) * 4;
            *(float4*)&Bs[r][c4] = *(const float4*)(Bp + r * CC_ + c4);
        }
        __syncthreads();

#pragma unroll
        for (int k = 0; k < BK; k++) {
            float a[8], b[8];
            *(float4*)&a[0] = *(const float4*)&As[k][ty * 8];
            *(float4*)&a[4] = *(const float4*)&As[k][ty * 8 + 4];
            *(float4*)&b[0] = *(const float4*)&Bs[k][tx * 8];
            *(float4*)&b[4] = *(const float4*)&Bs[k][tx * 8 + 4];
#pragma unroll
            for (int i = 0; i < 8; i++)
#pragma unroll
                for (int j = 0; j < 8; j++) acc[i][j] += a[i] * b[j];
        }
        __syncthreads();
    }

#pragma unroll
    for (int i = 0; i < 8; i++) {
        int row = by * BM + ty * 8 + i;
        int col = bx * BN + tx * 8;
#pragma unroll
        for (int j = 0; j < 8; j += 4) {
            float4 v;
            v.x = acc[i][j + 0] + linlb[col + j + 0];
            v.y = acc[i][j + 1] + linlb[col + j + 1];
            v.z = acc[i][j + 2] + linlb[col + j + 2];
            v.w = acc[i][j + 3] + linlb[col + j + 3];
            *(float4*)&out[(size_t)row * CC_ + col + j] = v;
        }
    }
}

// ---------------------------------------------------------------------------
extern "C" void kernel_launch(void* const* d_in, const int* in_sizes, int n_in,
                              void* d_out, int out_size) {
    const float* x           = (const float*)d_in[0];
    const float* edge_attr   = (const float*)d_in[1];
    const float* edge_weight = (const float*)d_in[2];
    const float* lin_W       = (const float*)d_in[3];
    const float* lin_b       = (const float*)d_in[4];
    const float* linl_W      = (const float*)d_in[5];
    const float* linl_b      = (const float*)d_in[6];
    const float* linr_W      = (const float*)d_in[7];
    const float* bond_W      = (const float*)d_in[8];
    const float* bond_b      = (const float*)d_in[9];
    const int*   edge_index  = (const int*)d_in[10];
    float*       out         = (float*)d_out;

    detect_kernel<<<1, 256>>>(edge_index);
    zero_kernel<<<20000, 256>>>();
    count_kernel<<<(EE_ + 255) / 256, 256>>>(edge_index);
    inv_kernel<<<(NN_ + 255) / 256, 256>>>();
    {
        dim3 grid(CC_ / BN, MTOT_ / BM);
        gemm_xl_kernel<<<grid, 256>>>(x, lin_W, lin_b);
    }
    msg_kernel<<<EE_, 256>>>(edge_attr, bond_W, bond_b, edge_weight, edge_index);
    {
        dim3 grid(CC_ / BN, MTOT_ / BM);
        gemm_out_kernel<<<grid, 256>>>(x, linl_W, linl_b, linr_W, out);
    }
}

// round 4
// speedup vs baseline: 1.6379x; 1.6379x over previous
#include <cuda_runtime.h>
#include <cuda_bf16.h>
#include <math.h>
#include <stdint.h>

// Problem constants
#define RC_    4        // R*CH
#define NN_    20000
#define EE_    100000
#define CC_    256
#define MTOT_  80000    // R*CH*N

// ---------------------------------------------------------------------------
// Scratch (static device globals; no runtime allocation)
// ---------------------------------------------------------------------------
__device__ __align__(256) float g_xl[MTOT_ * CC_];     // x @ lin_W + lin_b
__device__ __align__(256) float g_sums[MTOT_ * CC_];   // scatter accumulator
__device__ __align__(256) float g_cnt[NN_];
__device__ __align__(256) float g_inv[NN_];
__device__ int g_is64;

__device__ __align__(256) __nv_bfloat16 g_xhi[MTOT_ * CC_];
__device__ __align__(256) __nv_bfloat16 g_xlo[MTOT_ * CC_];
__device__ __align__(256) __nv_bfloat16 g_ahi[MTOT_ * CC_];
__device__ __align__(256) __nv_bfloat16 g_alo[MTOT_ * CC_];
// Transposed split weights, [n][k] layout
__device__ __align__(256) __nv_bfloat16 g_WT0[CC_ * CC_];  // lin_W  hi
__device__ __align__(256) __nv_bfloat16 g_WT1[CC_ * CC_];  // lin_W  lo
__device__ __align__(256) __nv_bfloat16 g_WT2[CC_ * CC_];  // linl_W hi
__device__ __align__(256) __nv_bfloat16 g_WT3[CC_ * CC_];  // linl_W lo
__device__ __align__(256) __nv_bfloat16 g_WT4[CC_ * CC_];  // linr_W hi
__device__ __align__(256) __nv_bfloat16 g_WT5[CC_ * CC_];  // linr_W lo

// ---------------------------------------------------------------------------
// PTX helpers (all sm_80+ features; no sm_103a-only instructions)
// ---------------------------------------------------------------------------
__device__ __forceinline__ uint32_t smem_u32(const void* p) {
    uint32_t a;
    asm("{ .reg .u64 t; cvta.to.shared.u64 t, %1; cvt.u32.u64 %0, t; }"
        : "=r"(a) : "l"(p));
    return a;
}
__device__ __forceinline__ void cp16(uint32_t saddr, const void* g) {
    asm volatile("cp.async.cg.shared.global [%0], [%1], 16;"
                 :: "r"(saddr), "l"(g) : "memory");
}
#define CP_COMMIT() asm volatile("cp.async.commit_group;" ::: "memory")
#define CP_WAIT1()  asm volatile("cp.async.wait_group 1;" ::: "memory")
#define CP_WAIT0()  asm volatile("cp.async.wait_group 0;" ::: "memory")

#define LDSM4(r, addr) \
    asm volatile("ldmatrix.sync.aligned.m8n8.x4.shared.b16 {%0,%1,%2,%3}, [%4];" \
                 : "=r"((r)[0]), "=r"((r)[1]), "=r"((r)[2]), "=r"((r)[3]) \
                 : "r"(addr))

#define MMA16816(d, a, b0, b1) \
    asm volatile("mma.sync.aligned.m16n8k16.row.col.f32.bf16.bf16.f32 " \
                 "{%0,%1,%2,%3}, {%4,%5,%6,%7}, {%8,%9}, {%0,%1,%2,%3};" \
                 : "+f"((d)[0]), "+f"((d)[1]), "+f"((d)[2]), "+f"((d)[3]) \
                 : "r"((a)[0]), "r"((a)[1]), "r"((a)[2]), "r"((a)[3]), \
                   "r"(b0), "r"(b1))

// SMEM geometry: padded 80B row stride -> conflict-free ldmatrix
#define ROWB        80
#define TILE_BYTES  10240        // 128 rows * 80B
#define STAGE_BYTES 20480        // A tile + B tile
#define SMEM_BYTES  40960        // 2 stages

// ---------------------------------------------------------------------------
// edge_index dtype detect + index load
// ---------------------------------------------------------------------------
__global__ void detect_kernel(const int* __restrict__ ei32) {
    __shared__ int any_nonzero;
    if (threadIdx.x == 0) any_nonzero = 0;
    __syncthreads();
    if (ei32[2 * threadIdx.x + 1] != 0) atomicOr(&any_nonzero, 1);
    __syncthreads();
    if (threadIdx.x == 0) g_is64 = (any_nonzero == 0) ? 1 : 0;
}
__device__ __forceinline__ int load_idx(const int* ei32, int pos) {
    int v = g_is64 ? ei32[2 * pos] : ei32[pos];
    return min(max(v, 0), NN_ - 1);
}

// ---------------------------------------------------------------------------
__global__ void zero_kernel() {
    int idx = blockIdx.x * 256 + threadIdx.x;
    ((float4*)g_sums)[idx] = make_float4(0.f, 0.f, 0.f, 0.f);
    if (idx < NN_) g_cnt[idx] = 0.f;
}
__global__ void count_kernel(const int* __restrict__ ei32) {
    int e = blockIdx.x * 256 + threadIdx.x;
    if (e < EE_) atomicAdd(&g_cnt[load_idx(ei32, EE_ + e)], 1.0f);
}
__global__ void inv_kernel() {
    int n = blockIdx.x * 256 + threadIdx.x;
    if (n < NN_) g_inv[n] = 1.0f / fmaxf(g_cnt[n], 1.0f);
}

// ---------------------------------------------------------------------------
// fp32 -> (hi,lo) bf16 split
// ---------------------------------------------------------------------------
__device__ __forceinline__ void split4(float4 v, __nv_bfloat162* H, __nv_bfloat162* L,
                                       size_t i4) {
    __nv_bfloat16 h0 = __float2bfloat16_rn(v.x);
    __nv_bfloat16 h1 = __float2bfloat16_rn(v.y);
    __nv_bfloat16 h2 = __float2bfloat16_rn(v.z);
    __nv_bfloat16 h3 = __float2bfloat16_rn(v.w);
    __nv_bfloat162 p;
    p.x = h0; p.y = h1; H[i4 * 2 + 0] = p;
    p.x = h2; p.y = h3; H[i4 * 2 + 1] = p;
    p.x = __float2bfloat16_rn(v.x - __bfloat162float(h0));
    p.y = __float2bfloat16_rn(v.y - __bfloat162float(h1));
    L[i4 * 2 + 0] = p;
    p.x = __float2bfloat16_rn(v.z - __bfloat162float(h2));
    p.y = __float2bfloat16_rn(v.w - __bfloat162float(h3));
    L[i4 * 2 + 1] = p;
}

__global__ void xsplit_kernel(const float* __restrict__ x) {
    size_t i4 = (size_t)blockIdx.x * 256 + threadIdx.x;
    float4 v = ((const float4*)x)[i4];
    split4(v, (__nv_bfloat162*)g_xhi, (__nv_bfloat162*)g_xlo, i4);
}

__global__ void aggsplit_kernel() {
    size_t i4 = (size_t)blockIdx.x * 256 + threadIdx.x;
    int row = (int)(i4 >> 6);
    float s = g_inv[row % NN_];
    float4 v = ((const float4*)g_sums)[i4];
    v.x *= s; v.y *= s; v.z *= s; v.w *= s;
    split4(v, (__nv_bfloat162*)g_ahi, (__nv_bfloat162*)g_alo, i4);
}

__global__ void wprep_kernel(const float* __restrict__ W0,
                             const float* __restrict__ W1,
                             const float* __restrict__ W2) {
    const float* W = (blockIdx.y == 0) ? W0 : ((blockIdx.y == 1) ? W1 : W2);
    __nv_bfloat16* H = (blockIdx.y == 0) ? g_WT0 : ((blockIdx.y == 1) ? g_WT2 : g_WT4);
    __nv_bfloat16* L = (blockIdx.y == 0) ? g_WT1 : ((blockIdx.y == 1) ? g_WT3 : g_WT5);
    int k = blockIdx.x, n = threadIdx.x;
    float v = W[k * CC_ + n];
    __nv_bfloat16 h = __float2bfloat16_rn(v);
    H[n * CC_ + k] = h;
    L[n * CC_ + k] = __float2bfloat16_rn(v - __bfloat162float(h));
}

// ---------------------------------------------------------------------------
// bf16 mma.sync GEMM. CTA tile 128x128, BK=32, 8 warps (2M x 4N),
// warp tile 64x32 = 4x4 m16n8k16. fp32 accum in registers.
// which==0: g_xl = [xhi,xlo,xhi] @ [W0,W0,W1]^T + lin_b          (K=768)
// which==1: out  = [ahi,alo,ahi,xhi,xlo,xhi] @ [W2,W2,W3,W4,W4,W5]^T + linl_b (K=1536)
// ---------------------------------------------------------------------------
__device__ __forceinline__ void load_stage(char* smem, int s, int tid,
                                           const __nv_bfloat16* Ag,
                                           const __nv_bfloat16* Bg) {
    uint32_t a32 = smem_u32(smem + s * STAGE_BYTES);
    uint32_t b32 = a32 + TILE_BYTES;
#pragma unroll
    for (int i = 0; i < 2; i++) {
        int idx = tid + i * 256;       // 0..511
        int r = idx >> 2, ch = idx & 3;
        cp16(a32 + r * ROWB + ch * 16,
             (const char*)Ag + ((size_t)r * CC_ + ch * 8) * 2);
    }
#pragma unroll
    for (int i = 0; i < 2; i++) {
        int idx = tid + i * 256;
        int r = idx >> 2, ch = idx & 3;
        cp16(b32 + r * ROWB + ch * 16,
             (const char*)Bg + ((size_t)r * CC_ + ch * 8) * 2);
    }
}

__global__ __launch_bounds__(256, 2) void mma_gemm(
    int which, const float* __restrict__ bias, float* __restrict__ out_ext)
{
    extern __shared__ __align__(128) char smem[];
    const int tid = threadIdx.x, lane = tid & 31, wid = tid >> 5;
    const int warp_m = wid & 1, warp_n = wid >> 1;
    const int bx = blockIdx.x, by = blockIdx.y;
    const int g = lane >> 3, lr = lane & 7;

    const __nv_bfloat16 *Aseg[6], *Bseg[6];
    int nseg;
    float* outp;
    if (which == 0) {
        Aseg[0] = g_xhi; Aseg[1] = g_xlo; Aseg[2] = g_xhi;
        Bseg[0] = g_WT0; Bseg[1] = g_WT0; Bseg[2] = g_WT1;
        nseg = 3; outp = g_xl;
    } else {
        Aseg[0] = g_ahi; Aseg[1] = g_alo; Aseg[2] = g_ahi;
        Aseg[3] = g_xhi; Aseg[4] = g_xlo; Aseg[5] = g_xhi;
        Bseg[0] = g_WT2; Bseg[1] = g_WT2; Bseg[2] = g_WT3;
        Bseg[3] = g_WT4; Bseg[4] = g_WT4; Bseg[5] = g_WT5;
        nseg = 6; outp = out_ext;
    }
    const int NC = nseg * 8;    // BK=32 chunks per 256-K segment

    float acc[4][4][4];
#pragma unroll
    for (int mt = 0; mt < 4; mt++)
#pragma unroll
        for (int nt = 0; nt < 4; nt++)
#pragma unroll
            for (int q = 0; q < 4; q++) acc[mt][nt][q] = 0.f;

    const size_t arow = (size_t)by * 128 * CC_;
    const size_t brow = (size_t)bx * 128 * CC_;

    load_stage(smem, 0, tid, Aseg[0] + arow, Bseg[0] + brow);
    CP_COMMIT();

    for (int c = 0; c < NC; c++) {
        if (c + 1 < NC) {
            int seg = (c + 1) >> 3, ko = ((c + 1) & 7) * 32;
            load_stage(smem, (c + 1) & 1, tid,
                       Aseg[seg] + arow + ko, Bseg[seg] + brow + ko);
            CP_COMMIT();
            CP_WAIT1();
        } else {
            CP_WAIT0();
        }
        __syncthreads();

        uint32_t a_base = smem_u32(smem + (c & 1) * STAGE_BYTES);
        uint32_t b_base = a_base + TILE_BYTES;
#pragma unroll
        for (int ks = 0; ks < 2; ks++) {
            uint32_t a[4][4];
#pragma unroll
            for (int mt = 0; mt < 4; mt++) {
                int row = warp_m * 64 + mt * 16 + (g & 1) * 8 + lr;
                LDSM4(a[mt], a_base + row * ROWB + ks * 32 + (g >> 1) * 16);
            }
            uint32_t b[2][4];
#pragma unroll
            for (int p = 0; p < 2; p++) {
                int row = warp_n * 32 + p * 16 + ((g >> 1) & 1) * 8 + lr;
                LDSM4(b[p], b_base + row * ROWB + ks * 32 + (g & 1) * 16);
            }
#pragma unroll
            for (int mt = 0; mt < 4; mt++)
#pragma unroll
                for (int nt = 0; nt < 4; nt++) {
                    int p = nt >> 1, h = (nt & 1) * 2;
                    MMA16816(acc[mt][nt], a[mt], b[p][h], b[p][h + 1]);
                }
        }
        __syncthreads();
    }

    // Epilogue: c0,c1 -> (row=tg, col=tig*2,+1); c2,c3 -> row+8
    const int tg = lane >> 2, tig = lane & 3;
#pragma unroll
    for (int mt = 0; mt < 4; mt++) {
#pragma unroll
        for (int nt = 0; nt < 4; nt++) {
            int row = by * 128 + warp_m * 64 + mt * 16 + tg;
            int col = bx * 128 + warp_n * 32 + nt * 8 + tig * 2;
            float b0 = bias[col], b1 = bias[col + 1];
            float2 v0, v1;
            v0.x = acc[mt][nt][0] + b0; v0.y = acc[mt][nt][1] + b1;
            v1.x = acc[mt][nt][2] + b0; v1.y = acc[mt][nt][3] + b1;
            *(float2*)(outp + (size_t)row * CC_ + col) = v0;
            *(float2*)(outp + (size_t)(row + 8) * CC_ + col) = v1;
        }
    }
}

// ---------------------------------------------------------------------------
// Message + scatter: block per edge, thread = channel
// ---------------------------------------------------------------------------
__global__ __launch_bounds__(256) void msg_kernel(
    const float* __restrict__ edge_attr,    // (E,16)
    const float* __restrict__ bond_W,       // (16,256)
    const float* __restrict__ bond_b,       // (256)
    const float* __restrict__ edge_weight,  // (RC, E)
    const int* __restrict__ ei32)
{
    const int e = blockIdx.x;
    const int c = threadIdx.x;

    __shared__ float ea[16];
    if (c < 16) ea[c] = edge_attr[e * 16 + c];
    __syncthreads();

    float emb = bond_b[c];
#pragma unroll
    for (int d = 0; d < 16; d++) emb += ea[d] * bond_W[d * CC_ + c];

    const int src = load_idx(ei32, e);
    const int dst = load_idx(ei32, EE_ + e);

#pragma unroll
    for (int rc = 0; rc < RC_; rc++) {
        float w = edge_weight[rc * EE_ + e];
        float v = g_xl[(size_t)(rc * NN_ + src) * CC_ + c] + emb;
        float gg = 0.5f * v * (1.0f + erff(v * 0.70710678118654752f)) * w;
        atomicAdd(&g_sums[(size_t)(rc * NN_ + dst) * CC_ + c], gg);
    }
}

// ---------------------------------------------------------------------------
extern "C" void kernel_launch(void* const* d_in, const int* in_sizes, int n_in,
                              void* d_out, int out_size) {
    const float* x           = (const float*)d_in[0];
    const float* edge_attr   = (const float*)d_in[1];
    const float* edge_weight = (const float*)d_in[2];
    const float* lin_W       = (const float*)d_in[3];
    const float* lin_b       = (const float*)d_in[4];
    const float* linl_W      = (const float*)d_in[5];
    const float* linl_b      = (const float*)d_in[6];
    const float* linr_W      = (const float*)d_in[7];
    const float* bond_W      = (const float*)d_in[8];
    const float* bond_b      = (const float*)d_in[9];
    const int*   edge_index  = (const int*)d_in[10];
    float*       out         = (float*)d_out;

    detect_kernel<<<1, 256>>>(edge_index);
    zero_kernel<<<20000, 256>>>();
    count_kernel<<<(EE_ + 255) / 256, 256>>>(edge_index);
    inv_kernel<<<(NN_ + 255) / 256, 256>>>();
    wprep_kernel<<<dim3(256, 3), 256>>>(lin_W, linl_W, linr_W);
    xsplit_kernel<<<20000, 256>>>(x);

    {
        dim3 grid(2, MTOT_ / 128);
        mma_gemm<<<grid, 256, SMEM_BYTES>>>(0, lin_b, nullptr);   // -> g_xl
    }
    msg_kernel<<<EE_, 256>>>(edge_attr, bond_W, bond_b, edge_weight, edge_index);
    aggsplit_kernel<<<20000, 256>>>();
    {
        dim3 grid(2, MTOT_ / 128);
        mma_gemm<<<grid, 256, SMEM_BYTES>>>(1, linl_b, out);      // -> out
    }
}

// round 6
// speedup vs baseline: 1.6717x; 1.0206x over previous
#include <cuda_runtime.h>
#include <cuda_bf16.h>
#include <math.h>
#include <stdint.h>

// Problem constants
#define RC_    4        // R*CH
#define NN_    20000
#define EE_    100000
#define CC_    256
#define MTOT_  80000    // R*CH*N

// ---------------------------------------------------------------------------
// Scratch (static device globals; no runtime allocation)
// ---------------------------------------------------------------------------
__device__ __align__(256) float g_xl[MTOT_ * CC_];     // x @ lin_W + lin_b
__device__ int g_is64;

// CSR scratch
__device__ __align__(256) int g_icnt[NN_];             // zero-init; reset by scan
__device__ __align__(256) int g_rowstart[NN_ + 1];
__device__ __align__(256) int g_pos[NN_];
__device__ __align__(256) int g_ebkt[EE_];

__device__ __align__(256) __nv_bfloat16 g_xhi[MTOT_ * CC_];
__device__ __align__(256) __nv_bfloat16 g_xlo[MTOT_ * CC_];
__device__ __align__(256) __nv_bfloat16 g_ahi[MTOT_ * CC_];
__device__ __align__(256) __nv_bfloat16 g_alo[MTOT_ * CC_];
// Transposed split weights, [n][k] layout
__device__ __align__(256) __nv_bfloat16 g_WT0[CC_ * CC_];  // lin_W  hi
__device__ __align__(256) __nv_bfloat16 g_WT1[CC_ * CC_];  // lin_W  lo
__device__ __align__(256) __nv_bfloat16 g_WT2[CC_ * CC_];  // linl_W hi
__device__ __align__(256) __nv_bfloat16 g_WT3[CC_ * CC_];  // linl_W lo
__device__ __align__(256) __nv_bfloat16 g_WT4[CC_ * CC_];  // linr_W hi
__device__ __align__(256) __nv_bfloat16 g_WT5[CC_ * CC_];  // linr_W lo

// ---------------------------------------------------------------------------
// PTX helpers (sm_80+ only; no sm_103a-exclusive instructions)
// ---------------------------------------------------------------------------
__device__ __forceinline__ uint32_t smem_u32(const void* p) {
    uint32_t a;
    asm("{ .reg .u64 t; cvta.to.shared.u64 t, %1; cvt.u32.u64 %0, t; }"
        : "=r"(a) : "l"(p));
    return a;
}
__device__ __forceinline__ void cp16(uint32_t saddr, const void* g) {
    asm volatile("cp.async.cg.shared.global [%0], [%1], 16;"
                 :: "r"(saddr), "l"(g) : "memory");
}
#define CP_COMMIT() asm volatile("cp.async.commit_group;" ::: "memory")
#define CP_WAIT1()  asm volatile("cp.async.wait_group 1;" ::: "memory")
#define CP_WAIT0()  asm volatile("cp.async.wait_group 0;" ::: "memory")

#define LDSM4(r, addr) \
    asm volatile("ldmatrix.sync.aligned.m8n8.x4.shared.b16 {%0,%1,%2,%3}, [%4];" \
                 : "=r"((r)[0]), "=r"((r)[1]), "=r"((r)[2]), "=r"((r)[3]) \
                 : "r"(addr))

#define MMA16816(d, a, b0, b1) \
    asm volatile("mma.sync.aligned.m16n8k16.row.col.f32.bf16.bf16.f32 " \
                 "{%0,%1,%2,%3}, {%4,%5,%6,%7}, {%8,%9}, {%0,%1,%2,%3};" \
                 : "+f"((d)[0]), "+f"((d)[1]), "+f"((d)[2]), "+f"((d)[3]) \
                 : "r"((a)[0]), "r"((a)[1]), "r"((a)[2]), "r"((a)[3]), \
                   "r"(b0), "r"(b1))

// SMEM geometry: padded 80B row stride -> conflict-free ldmatrix
#define ROWB        80
#define TILE_BYTES  10240        // 128 rows * 80B
#define STAGE_BYTES 20480        // A tile + B tile
#define SMEM_BYTES  40960        // 2 stages

// ---------------------------------------------------------------------------
// edge_index dtype detect + index load
// ---------------------------------------------------------------------------
__global__ void detect_kernel(const int* __restrict__ ei32) {
    __shared__ int any_nonzero;
    if (threadIdx.x == 0) any_nonzero = 0;
    __syncthreads();
    if (ei32[2 * threadIdx.x + 1] != 0) atomicOr(&any_nonzero, 1);
    __syncthreads();
    if (threadIdx.x == 0) g_is64 = (any_nonzero == 0) ? 1 : 0;
}
__device__ __forceinline__ int load_idx(const int* ei32, int pos) {
    int v = g_is64 ? ei32[2 * pos] : ei32[pos];
    return min(max(v, 0), NN_ - 1);
}

// ---------------------------------------------------------------------------
// CSR build: histogram -> scan (+ reset histogram) -> bucket fill
// ---------------------------------------------------------------------------
__global__ void icount_kernel(const int* __restrict__ ei32) {
    int e = blockIdx.x * 256 + threadIdx.x;
    if (e < EE_) atomicAdd(&g_icnt[load_idx(ei32, EE_ + e)], 1);
}

__global__ __launch_bounds__(1024) void scan_kernel() {
    __shared__ int buf[1024];
    __shared__ int carry;
    const int tid = threadIdx.x;
    if (tid == 0) carry = 0;
    __syncthreads();
    for (int chunk = 0; chunk < (NN_ + 1023) / 1024; chunk++) {
        int i = chunk * 1024 + tid;
        int v = (i < NN_) ? g_icnt[i] : 0;
        if (i < NN_) g_icnt[i] = 0;          // reset for next graph replay
        int add = carry;
        buf[tid] = v;
        __syncthreads();
        for (int off = 1; off < 1024; off <<= 1) {
            int t = (tid >= off) ? buf[tid - off] : 0;
            __syncthreads();
            buf[tid] += t;
            __syncthreads();
        }
        if (i < NN_) {
            int excl = add + buf[tid] - v;
            g_rowstart[i] = excl;
            g_pos[i] = excl;
        }
        __syncthreads();
        if (tid == 0) carry = add + buf[1023];
        __syncthreads();
    }
    if (tid == 0) g_rowstart[NN_] = carry;   // == EE_
}

__global__ void fill_kernel(const int* __restrict__ ei32) {
    int e = blockIdx.x * 256 + threadIdx.x;
    if (e < EE_) {
        int dst = load_idx(ei32, EE_ + e);
        int p = atomicAdd(&g_pos[dst], 1);
        g_ebkt[p] = e;
    }
}

// ---------------------------------------------------------------------------
// fp32 -> (hi,lo) bf16 split
// ---------------------------------------------------------------------------
__device__ __forceinline__ void split4(float4 v, __nv_bfloat162* H, __nv_bfloat162* L,
                                       size_t i4) {
    __nv_bfloat16 h0 = __float2bfloat16_rn(v.x);
    __nv_bfloat16 h1 = __float2bfloat16_rn(v.y);
    __nv_bfloat16 h2 = __float2bfloat16_rn(v.z);
    __nv_bfloat16 h3 = __float2bfloat16_rn(v.w);
    __nv_bfloat162 p;
    p.x = h0; p.y = h1; H[i4 * 2 + 0] = p;
    p.x = h2; p.y = h3; H[i4 * 2 + 1] = p;
    p.x = __float2bfloat16_rn(v.x - __bfloat162float(h0));
    p.y = __float2bfloat16_rn(v.y - __bfloat162float(h1));
    L[i4 * 2 + 0] = p;
    p.x = __float2bfloat16_rn(v.z - __bfloat162float(h2));
    p.y = __float2bfloat16_rn(v.w - __bfloat162float(h3));
    L[i4 * 2 + 1] = p;
}

__global__ void xsplit_kernel(const float* __restrict__ x) {
    size_t i4 = (size_t)blockIdx.x * 256 + threadIdx.x;
    float4 v = ((const float4*)x)[i4];
    split4(v, (__nv_bfloat162*)g_xhi, (__nv_bfloat162*)g_xlo, i4);
}

__global__ void wprep_kernel(const float* __restrict__ W0,
                             const float* __restrict__ W1,
                             const float* __restrict__ W2) {
    const float* W = (blockIdx.y == 0) ? W0 : ((blockIdx.y == 1) ? W1 : W2);
    __nv_bfloat16* H = (blockIdx.y == 0) ? g_WT0 : ((blockIdx.y == 1) ? g_WT2 : g_WT4);
    __nv_bfloat16* L = (blockIdx.y == 0) ? g_WT1 : ((blockIdx.y == 1) ? g_WT3 : g_WT5);
    int k = blockIdx.x, n = threadIdx.x;
    float v = W[k * CC_ + n];
    __nv_bfloat16 h = __float2bfloat16_rn(v);
    H[n * CC_ + k] = h;
    L[n * CC_ + k] = __float2bfloat16_rn(v - __bfloat162float(h));
}

// ---------------------------------------------------------------------------
// Fused message gather: block = dst node, thread = channel.
// Accumulates GELU(x_l[src]+emb)*w over incident edges for all 4 (r,ch),
// divides by degree, writes bf16 hi/lo split of agg directly.
// No atomics, no zero-fill, no separate aggsplit.
// ---------------------------------------------------------------------------
__global__ __launch_bounds__(256) void gather_kernel(
    const float* __restrict__ edge_attr,    // (E,16)
    const float* __restrict__ bond_W,       // (16,256)
    const float* __restrict__ bond_b,       // (256)
    const float* __restrict__ edge_weight,  // (RC, E)
    const int* __restrict__ ei32)
{
    const int n = blockIdx.x;
    const int c = threadIdx.x;

    float bw[16];
#pragma unroll
    for (int d = 0; d < 16; d++) bw[d] = bond_W[d * CC_ + c];
    const float bb = bond_b[c];

    const int s0 = g_rowstart[n];
    const int s1 = g_rowstart[n + 1];
    const int deg = s1 - s0;

    float acc0 = 0.f, acc1 = 0.f, acc2 = 0.f, acc3 = 0.f;

    for (int i = s0; i < s1; i++) {
        const int e = g_ebkt[i];
        const int src = load_idx(ei32, e);

        float emb = bb;
#pragma unroll
        for (int d = 0; d < 16; d++)
            emb = fmaf(__ldg(&edge_attr[e * 16 + d]), bw[d], emb);

        const float w0 = __ldg(&edge_weight[0 * EE_ + e]);
        const float w1 = __ldg(&edge_weight[1 * EE_ + e]);
        const float w2 = __ldg(&edge_weight[2 * EE_ + e]);
        const float w3 = __ldg(&edge_weight[3 * EE_ + e]);

        const float* xr = g_xl + (size_t)src * CC_ + c;
        const size_t rs = (size_t)NN_ * CC_;
        float v0 = xr[0 * rs] + emb;
        float v1 = xr[1 * rs] + emb;
        float v2 = xr[2 * rs] + emb;
        float v3 = xr[3 * rs] + emb;
        const float k = 0.70710678118654752f;
        acc0 += 0.5f * v0 * (1.0f + erff(v0 * k)) * w0;
        acc1 += 0.5f * v1 * (1.0f + erff(v1 * k)) * w1;
        acc2 += 0.5f * v2 * (1.0f + erff(v2 * k)) * w2;
        acc3 += 0.5f * v3 * (1.0f + erff(v3 * k)) * w3;
    }

    const float s = 1.0f / (float)max(deg, 1);
    float a[4] = {acc0 * s, acc1 * s, acc2 * s, acc3 * s};
#pragma unroll
    for (int rc = 0; rc < RC_; rc++) {
        size_t off = (size_t)(rc * NN_ + n) * CC_ + c;
        __nv_bfloat16 h = __float2bfloat16_rn(a[rc]);
        g_ahi[off] = h;
        g_alo[off] = __float2bfloat16_rn(a[rc] - __bfloat162float(h));
    }
}

// ---------------------------------------------------------------------------
// bf16 mma.sync GEMM. CTA tile 128x128, BK=32, 8 warps (2M x 4N),
// warp tile 64x32 = 4x4 m16n8k16. fp32 accum in registers.
// which==0: g_xl = [xhi,xlo,xhi] @ [W0,W0,W1]^T + lin_b          (K=768)
// which==1: out  = [ahi,alo,ahi,xhi,xlo,xhi] @ [W2,W2,W3,W4,W4,W5]^T + linl_b (K=1536)
// ---------------------------------------------------------------------------
__device__ __forceinline__ void load_stage(char* smem, int s, int tid,
                                           const __nv_bfloat16* Ag,
                                           const __nv_bfloat16* Bg) {
    uint32_t a32 = smem_u32(smem + s * STAGE_BYTES);
    uint32_t b32 = a32 + TILE_BYTES;
#pragma unroll
    for (int i = 0; i < 2; i++) {
        int idx = tid + i * 256;       // 0..511
        int r = idx >> 2, ch = idx & 3;
        cp16(a32 + r * ROWB + ch * 16,
             (const char*)Ag + ((size_t)r * CC_ + ch * 8) * 2);
    }
#pragma unroll
    for (int i = 0; i < 2; i++) {
        int idx = tid + i * 256;
        int r = idx >> 2, ch = idx & 3;
        cp16(b32 + r * ROWB + ch * 16,
             (const char*)Bg + ((size_t)r * CC_ + ch * 8) * 2);
    }
}

__global__ __launch_bounds__(256, 2) void mma_gemm(
    int which, const float* __restrict__ bias, float* __restrict__ out_ext)
{
    extern __shared__ __align__(128) char smem[];
    const int tid = threadIdx.x, lane = tid & 31, wid = tid >> 5;
    const int warp_m = wid & 1, warp_n = wid >> 1;
    const int bx = blockIdx.x, by = blockIdx.y;
    const int g = lane >> 3, lr = lane & 7;

    const __nv_bfloat16 *Aseg[6], *Bseg[6];
    int nseg;
    float* outp;
    if (which == 0) {
        Aseg[0] = g_xhi; Aseg[1] = g_xlo; Aseg[2] = g_xhi;
        Bseg[0] = g_WT0; Bseg[1] = g_WT0; Bseg[2] = g_WT1;
        nseg = 3; outp = g_xl;
    } else {
        Aseg[0] = g_ahi; Aseg[1] = g_alo; Aseg[2] = g_ahi;
        Aseg[3] = g_xhi; Aseg[4] = g_xlo; Aseg[5] = g_xhi;
        Bseg[0] = g_WT2; Bseg[1] = g_WT2; Bseg[2] = g_WT3;
        Bseg[3] = g_WT4; Bseg[4] = g_WT4; Bseg[5] = g_WT5;
        nseg = 6; outp = out_ext;
    }
    const int NC = nseg * 8;    // BK=32 chunks per 256-K segment

    float acc[4][4][4];
#pragma unroll
    for (int mt = 0; mt < 4; mt++)
#pragma unroll
        for (int nt = 0; nt < 4; nt++)
#pragma unroll
            for (int q = 0; q < 4; q++) acc[mt][nt][q] = 0.f;

    const size_t arow = (size_t)by * 128 * CC_;
    const size_t brow = (size_t)bx * 128 * CC_;

    load_stage(smem, 0, tid, Aseg[0] + arow, Bseg[0] + brow);
    CP_COMMIT();

    for (int c = 0; c < NC; c++) {
        if (c + 1 < NC) {
            int seg = (c + 1) >> 3, ko = ((c + 1) & 7) * 32;
            load_stage(smem, (c + 1) & 1, tid,
                       Aseg[seg] + arow + ko, Bseg[seg] + brow + ko);
            CP_COMMIT();
            CP_WAIT1();
        } else {
            CP_WAIT0();
        }
        __syncthreads();

        uint32_t a_base = smem_u32(smem + (c & 1) * STAGE_BYTES);
        uint32_t b_base = a_base + TILE_BYTES;
#pragma unroll
        for (int ks = 0; ks < 2; ks++) {
            uint32_t a[4][4];
#pragma unroll
            for (int mt = 0; mt < 4; mt++) {
                int row = warp_m * 64 + mt * 16 + (g & 1) * 8 + lr;
                LDSM4(a[mt], a_base + row * ROWB + ks * 32 + (g >> 1) * 16);
            }
            uint32_t b[2][4];
#pragma unroll
            for (int p = 0; p < 2; p++) {
                int row = warp_n * 32 + p * 16 + ((g >> 1) & 1) * 8 + lr;
                LDSM4(b[p], b_base + row * ROWB + ks * 32 + (g & 1) * 16);
            }
#pragma unroll
            for (int mt = 0; mt < 4; mt++)
#pragma unroll
                for (int nt = 0; nt < 4; nt++) {
                    int p = nt >> 1, h = (nt & 1) * 2;
                    MMA16816(acc[mt][nt], a[mt], b[p][h], b[p][h + 1]);
                }
        }
        __syncthreads();
    }

    const int tg = lane >> 2, tig = lane & 3;
#pragma unroll
    for (int mt = 0; mt < 4; mt++) {
#pragma unroll
        for (int nt = 0; nt < 4; nt++) {
            int row = by * 128 + warp_m * 64 + mt * 16 + tg;
            int col = bx * 128 + warp_n * 32 + nt * 8 + tig * 2;
            float b0 = bias[col], b1 = bias[col + 1];
            float2 v0, v1;
            v0.x = acc[mt][nt][0] + b0; v0.y = acc[mt][nt][1] + b1;
            v1.x = acc[mt][nt][2] + b0; v1.y = acc[mt][nt][3] + b1;
            *(float2*)(outp + (size_t)row * CC_ + col) = v0;
            *(float2*)(outp + (size_t)(row + 8) * CC_ + col) = v1;
        }
    }
}

// ---------------------------------------------------------------------------
extern "C" void kernel_launch(void* const* d_in, const int* in_sizes, int n_in,
                              void* d_out, int out_size) {
    const float* x           = (const float*)d_in[0];
    const float* edge_attr   = (const float*)d_in[1];
    const float* edge_weight = (const float*)d_in[2];
    const float* lin_W       = (const float*)d_in[3];
    const float* lin_b       = (const float*)d_in[4];
    const float* linl_W      = (const float*)d_in[5];
    const float* linl_b      = (const float*)d_in[6];
    const float* linr_W      = (const float*)d_in[7];
    const float* bond_W      = (const float*)d_in[8];
    const float* bond_b      = (const float*)d_in[9];
    const int*   edge_index  = (const int*)d_in[10];
    float*       out         = (float*)d_out;

    detect_kernel<<<1, 256>>>(edge_index);
    icount_kernel<<<(EE_ + 255) / 256, 256>>>(edge_index);
    scan_kernel<<<1, 1024>>>();
    fill_kernel<<<(EE_ + 255) / 256, 256>>>(edge_index);
    wprep_kernel<<<dim3(256, 3), 256>>>(lin_W, linl_W, linr_W);
    xsplit_kernel<<<20000, 256>>>(x);

    {
        dim3 grid(2, MTOT_ / 128);
        mma_gemm<<<grid, 256, SMEM_BYTES>>>(0, lin_b, nullptr);   // -> g_xl
    }
    gather_kernel<<<NN_, 256>>>(edge_attr, bond_W, bond_b, edge_weight, edge_index);
    {
        dim3 grid(2, MTOT_ / 128);
        mma_gemm<<<grid, 256, SMEM_BYTES>>>(1, linl_b, out);      // -> out
    }
}

// round 7
// speedup vs baseline: 1.9969x; 1.1945x over previous
#include <cuda_runtime.h>
#include <cuda_fp16.h>
#include <math.h>
#include <stdint.h>

// Problem constants
#define RC_    4        // R*CH
#define NN_    20000
#define EE_    100000
#define CC_    256
#define MTOT_  80000    // R*CH*N

// ---------------------------------------------------------------------------
// Scratch (static device globals; no runtime allocation)
// ---------------------------------------------------------------------------
__device__ __align__(256) float g_xl[MTOT_ * CC_];     // x @ lin_W + lin_b
__device__ int g_is64;

// CSR scratch
__device__ __align__(256) int g_icnt[NN_];             // zero-init; reset by scan
__device__ __align__(256) int g_rowstart[NN_ + 1];
__device__ __align__(256) int g_pos[NN_];
__device__ __align__(256) int g_ebkt[EE_];

// fp16 2-term split operands
__device__ __align__(256) __half g_xhi[MTOT_ * CC_];
__device__ __align__(256) __half g_xlo[MTOT_ * CC_];
__device__ __align__(256) __half g_ahi[MTOT_ * CC_];
__device__ __align__(256) __half g_alo[MTOT_ * CC_];
// Transposed fp16 weights, [n][k] layout (hi part only; 2-term scheme)
__device__ __align__(256) __half g_WT0[CC_ * CC_];  // lin_W
__device__ __align__(256) __half g_WT2[CC_ * CC_];  // linl_W
__device__ __align__(256) __half g_WT4[CC_ * CC_];  // linr_W

// ---------------------------------------------------------------------------
// PTX helpers (sm_80+ only)
// ---------------------------------------------------------------------------
__device__ __forceinline__ uint32_t smem_u32(const void* p) {
    uint32_t a;
    asm("{ .reg .u64 t; cvta.to.shared.u64 t, %1; cvt.u32.u64 %0, t; }"
        : "=r"(a) : "l"(p));
    return a;
}
__device__ __forceinline__ void cp16(uint32_t saddr, const void* g) {
    asm volatile("cp.async.cg.shared.global [%0], [%1], 16;"
                 :: "r"(saddr), "l"(g) : "memory");
}
#define CP_COMMIT() asm volatile("cp.async.commit_group;" ::: "memory")
#define CP_WAIT1()  asm volatile("cp.async.wait_group 1;" ::: "memory")
#define CP_WAIT0()  asm volatile("cp.async.wait_group 0;" ::: "memory")

#define LDSM4(r, addr) \
    asm volatile("ldmatrix.sync.aligned.m8n8.x4.shared.b16 {%0,%1,%2,%3}, [%4];" \
                 : "=r"((r)[0]), "=r"((r)[1]), "=r"((r)[2]), "=r"((r)[3]) \
                 : "r"(addr))

#define MMA16816(d, a, b0, b1) \
    asm volatile("mma.sync.aligned.m16n8k16.row.col.f32.f16.f16.f32 " \
                 "{%0,%1,%2,%3}, {%4,%5,%6,%7}, {%8,%9}, {%0,%1,%2,%3};" \
                 : "+f"((d)[0]), "+f"((d)[1]), "+f"((d)[2]), "+f"((d)[3]) \
                 : "r"((a)[0]), "r"((a)[1]), "r"((a)[2]), "r"((a)[3]), \
                   "r"(b0), "r"(b1))

// SMEM geometry: padded 80B row stride -> conflict-free ldmatrix
#define ROWB        80
#define TILE_BYTES  10240        // 128 rows * 80B
#define STAGE_BYTES 20480        // A tile + B tile
#define SMEM_BYTES  40960        // 2 stages

// ---------------------------------------------------------------------------
// edge_index dtype detect + index load
// ---------------------------------------------------------------------------
__global__ void detect_kernel(const int* __restrict__ ei32) {
    __shared__ int any_nonzero;
    if (threadIdx.x == 0) any_nonzero = 0;
    __syncthreads();
    if (ei32[2 * threadIdx.x + 1] != 0) atomicOr(&any_nonzero, 1);
    __syncthreads();
    if (threadIdx.x == 0) g_is64 = (any_nonzero == 0) ? 1 : 0;
}
__device__ __forceinline__ int load_idx(const int* ei32, int pos) {
    int v = g_is64 ? ei32[2 * pos] : ei32[pos];
    return min(max(v, 0), NN_ - 1);
}

// ---------------------------------------------------------------------------
// CSR build: histogram -> scan (+ reset histogram) -> bucket fill
// ---------------------------------------------------------------------------
__global__ void icount_kernel(const int* __restrict__ ei32) {
    int e = blockIdx.x * 256 + threadIdx.x;
    if (e < EE_) atomicAdd(&g_icnt[load_idx(ei32, EE_ + e)], 1);
}

__global__ __launch_bounds__(1024) void scan_kernel() {
    __shared__ int buf[1024];
    __shared__ int carry;
    const int tid = threadIdx.x;
    if (tid == 0) carry = 0;
    __syncthreads();
    for (int chunk = 0; chunk < (NN_ + 1023) / 1024; chunk++) {
        int i = chunk * 1024 + tid;
        int v = (i < NN_) ? g_icnt[i] : 0;
        if (i < NN_) g_icnt[i] = 0;          // reset for next graph replay
        int add = carry;
        buf[tid] = v;
        __syncthreads();
        for (int off = 1; off < 1024; off <<= 1) {
            int t = (tid >= off) ? buf[tid - off] : 0;
            __syncthreads();
            buf[tid] += t;
            __syncthreads();
        }
        if (i < NN_) {
            int excl = add + buf[tid] - v;
            g_rowstart[i] = excl;
            g_pos[i] = excl;
        }
        __syncthreads();
        if (tid == 0) carry = add + buf[1023];
        __syncthreads();
    }
    if (tid == 0) g_rowstart[NN_] = carry;   // == EE_
}

__global__ void fill_kernel(const int* __restrict__ ei32) {
    int e = blockIdx.x * 256 + threadIdx.x;
    if (e < EE_) {
        int dst = load_idx(ei32, EE_ + e);
        int p = atomicAdd(&g_pos[dst], 1);
        g_ebkt[p] = e;
    }
}

// ---------------------------------------------------------------------------
// fp32 -> (hi,lo) fp16 split
// ---------------------------------------------------------------------------
__device__ __forceinline__ void split4(float4 v, __half2* H, __half2* L, size_t i4) {
    __half h0 = __float2half_rn(v.x);
    __half h1 = __float2half_rn(v.y);
    __half h2 = __float2half_rn(v.z);
    __half h3 = __float2half_rn(v.w);
    __half2 p;
    p.x = h0; p.y = h1; H[i4 * 2 + 0] = p;
    p.x = h2; p.y = h3; H[i4 * 2 + 1] = p;
    p.x = __float2half_rn(v.x - __half2float(h0));
    p.y = __float2half_rn(v.y - __half2float(h1));
    L[i4 * 2 + 0] = p;
    p.x = __float2half_rn(v.z - __half2float(h2));
    p.y = __float2half_rn(v.w - __half2float(h3));
    L[i4 * 2 + 1] = p;
}

__global__ void xsplit_kernel(const float* __restrict__ x) {
    size_t i4 = (size_t)blockIdx.x * 256 + threadIdx.x;
    float4 v = ((const float4*)x)[i4];
    split4(v, (__half2*)g_xhi, (__half2*)g_xlo, i4);
}

// Transpose three 256x256 weights into [n][k] fp16
__global__ void wprep_kernel(const float* __restrict__ W0,
                             const float* __restrict__ W1,
                             const float* __restrict__ W2) {
    const float* W = (blockIdx.y == 0) ? W0 : ((blockIdx.y == 1) ? W1 : W2);
    __half* H = (blockIdx.y == 0) ? g_WT0 : ((blockIdx.y == 1) ? g_WT2 : g_WT4);
    int k = blockIdx.x, n = threadIdx.x;
    H[n * CC_ + k] = __float2half_rn(W[k * CC_ + n]);
}

// ---------------------------------------------------------------------------
// Fused message gather: block = dst node, thread = channel.
// ---------------------------------------------------------------------------
__global__ __launch_bounds__(256) void gather_kernel(
    const float* __restrict__ edge_attr,    // (E,16)
    const float* __restrict__ bond_W,       // (16,256)
    const float* __restrict__ bond_b,       // (256)
    const float* __restrict__ edge_weight,  // (RC, E)
    const int* __restrict__ ei32)
{
    const int n = blockIdx.x;
    const int c = threadIdx.x;

    float bw[16];
#pragma unroll
    for (int d = 0; d < 16; d++) bw[d] = bond_W[d * CC_ + c];
    const float bb = bond_b[c];

    const int s0 = g_rowstart[n];
    const int s1 = g_rowstart[n + 1];
    const int deg = s1 - s0;

    float acc0 = 0.f, acc1 = 0.f, acc2 = 0.f, acc3 = 0.f;

    for (int i = s0; i < s1; i++) {
        const int e = g_ebkt[i];
        const int src = load_idx(ei32, e);

        float emb = bb;
#pragma unroll
        for (int d = 0; d < 16; d++)
            emb = fmaf(__ldg(&edge_attr[e * 16 + d]), bw[d], emb);

        const float w0 = __ldg(&edge_weight[0 * EE_ + e]);
        const float w1 = __ldg(&edge_weight[1 * EE_ + e]);
        const float w2 = __ldg(&edge_weight[2 * EE_ + e]);
        const float w3 = __ldg(&edge_weight[3 * EE_ + e]);

        const float* xr = g_xl + (size_t)src * CC_ + c;
        const size_t rs = (size_t)NN_ * CC_;
        float v0 = xr[0 * rs] + emb;
        float v1 = xr[1 * rs] + emb;
        float v2 = xr[2 * rs] + emb;
        float v3 = xr[3 * rs] + emb;
        const float k = 0.70710678118654752f;
        acc0 += 0.5f * v0 * (1.0f + erff(v0 * k)) * w0;
        acc1 += 0.5f * v1 * (1.0f + erff(v1 * k)) * w1;
        acc2 += 0.5f * v2 * (1.0f + erff(v2 * k)) * w2;
        acc3 += 0.5f * v3 * (1.0f + erff(v3 * k)) * w3;
    }

    const float s = 1.0f / (float)max(deg, 1);
    float a[4] = {acc0 * s, acc1 * s, acc2 * s, acc3 * s};
#pragma unroll
    for (int rc = 0; rc < RC_; rc++) {
        size_t off = (size_t)(rc * NN_ + n) * CC_ + c;
        __half h = __float2half_rn(a[rc]);
        g_ahi[off] = h;
        g_alo[off] = __float2half_rn(a[rc] - __half2float(h));
    }
}

// ---------------------------------------------------------------------------
// fp16 mma.sync GEMM. CTA tile 128x128, BK=32, 8 warps (2M x 4N),
// warp tile 64x32 = 4x4 m16n8k16. fp32 accum in registers.
// which==0: g_xl = [xhi,xlo] @ [W0,W0]^T + lin_b                 (K=512)
// which==1: out  = [ahi,alo,xhi,xlo] @ [W2,W2,W4,W4]^T + linl_b  (K=1024)
// ---------------------------------------------------------------------------
__device__ __forceinline__ void load_stage(char* smem, int s, int tid,
                                           const __half* Ag, const __half* Bg) {
    uint32_t a32 = smem_u32(smem + s * STAGE_BYTES);
    uint32_t b32 = a32 + TILE_BYTES;
#pragma unroll
    for (int i = 0; i < 2; i++) {
        int idx = tid + i * 256;       // 0..511
        int r = idx >> 2, ch = idx & 3;
        cp16(a32 + r * ROWB + ch * 16,
             (const char*)Ag + ((size_t)r * CC_ + ch * 8) * 2);
    }
#pragma unroll
    for (int i = 0; i < 2; i++) {
        int idx = tid + i * 256;
        int r = idx >> 2, ch = idx & 3;
        cp16(b32 + r * ROWB + ch * 16,
             (const char*)Bg + ((size_t)r * CC_ + ch * 8) * 2);
    }
}

__global__ __launch_bounds__(256, 2) void mma_gemm(
    int which, const float* __restrict__ bias, float* __restrict__ out_ext)
{
    extern __shared__ __align__(128) char smem[];
    const int tid = threadIdx.x, lane = tid & 31, wid = tid >> 5;
    const int warp_m = wid & 1, warp_n = wid >> 1;
    const int bx = blockIdx.x, by = blockIdx.y;
    const int g = lane >> 3, lr = lane & 7;

    const __half *Aseg[4], *Bseg[4];
    int nseg;
    float* outp;
    if (which == 0) {
        Aseg[0] = g_xhi; Aseg[1] = g_xlo;
        Bseg[0] = g_WT0; Bseg[1] = g_WT0;
        nseg = 2; outp = g_xl;
    } else {
        Aseg[0] = g_ahi; Aseg[1] = g_alo; Aseg[2] = g_xhi; Aseg[3] = g_xlo;
        Bseg[0] = g_WT2; Bseg[1] = g_WT2; Bseg[2] = g_WT4; Bseg[3] = g_WT4;
        nseg = 4; outp = out_ext;
    }
    const int NC = nseg * 8;    // BK=32 chunks per 256-K segment

    float acc[4][4][4];
#pragma unroll
    for (int mt = 0; mt < 4; mt++)
#pragma unroll
        for (int nt = 0; nt < 4; nt++)
#pragma unroll
            for (int q = 0; q < 4; q++) acc[mt][nt][q] = 0.f;

    const size_t arow = (size_t)by * 128 * CC_;
    const size_t brow = (size_t)bx * 128 * CC_;

    load_stage(smem, 0, tid, Aseg[0] + arow, Bseg[0] + brow);
    CP_COMMIT();

    for (int c = 0; c < NC; c++) {
        if (c + 1 < NC) {
            int seg = (c + 1) >> 3, ko = ((c + 1) & 7) * 32;
            load_stage(smem, (c + 1) & 1, tid,
                       Aseg[seg] + arow + ko, Bseg[seg] + brow + ko);
            CP_COMMIT();
            CP_WAIT1();
        } else {
            CP_WAIT0();
        }
        __syncthreads();

        uint32_t a_base = smem_u32(smem + (c & 1) * STAGE_BYTES);
        uint32_t b_base = a_base + TILE_BYTES;
#pragma unroll
        for (int ks = 0; ks < 2; ks++) {
            uint32_t a[4][4];
#pragma unroll
            for (int mt = 0; mt < 4; mt++) {
                int row = warp_m * 64 + mt * 16 + (g & 1) * 8 + lr;
                LDSM4(a[mt], a_base + row * ROWB + ks * 32 + (g >> 1) * 16);
            }
            uint32_t b[2][4];
#pragma unroll
            for (int p = 0; p < 2; p++) {
                int row = warp_n * 32 + p * 16 + ((g >> 1) & 1) * 8 + lr;
                LDSM4(b[p], b_base + row * ROWB + ks * 32 + (g & 1) * 16);
            }
#pragma unroll
            for (int mt = 0; mt < 4; mt++)
#pragma unroll
                for (int nt = 0; nt < 4; nt++) {
                    int p = nt >> 1, h = (nt & 1) * 2;
                    MMA16816(acc[mt][nt], a[mt], b[p][h], b[p][h + 1]);
                }
        }
        __syncthreads();
    }

    const int tg = lane >> 2, tig = lane & 3;
#pragma unroll
    for (int mt = 0; mt < 4; mt++) {
#pragma unroll
        for (int nt = 0; nt < 4; nt++) {
            int row = by * 128 + warp_m * 64 + mt * 16 + tg;
            int col = bx * 128 + warp_n * 32 + nt * 8 + tig * 2;
            float b0 = bias[col], b1 = bias[col + 1];
            float2 v0, v1;
            v0.x = acc[mt][nt][0] + b0; v0.y = acc[mt][nt][1] + b1;
            v1.x = acc[mt][nt][2] + b0; v1.y = acc[mt][nt][3] + b1;
            *(float2*)(outp + (size_t)row * CC_ + col) = v0;
            *(float2*)(outp + (size_t)(row + 8) * CC_ + col) = v1;
        }
    }
}

// ---------------------------------------------------------------------------
extern "C" void kernel_launch(void* const* d_in, const int* in_sizes, int n_in,
                              void* d_out, int out_size) {
    const float* x           = (const float*)d_in[0];
    const float* edge_attr   = (const float*)d_in[1];
    const float* edge_weight = (const float*)d_in[2];
    const float* lin_W       = (const float*)d_in[3];
    const float* lin_b       = (const float*)d_in[4];
    const float* linl_W      = (const float*)d_in[5];
    const float* linl_b      = (const float*)d_in[6];
    const float* linr_W      = (const float*)d_in[7];
    const float* bond_W      = (const float*)d_in[8];
    const float* bond_b      = (const float*)d_in[9];
    const int*   edge_index  = (const int*)d_in[10];
    float*       out         = (float*)d_out;

    detect_kernel<<<1, 256>>>(edge_index);
    icount_kernel<<<(EE_ + 255) / 256, 256>>>(edge_index);
    scan_kernel<<<1, 1024>>>();
    fill_kernel<<<(EE_ + 255) / 256, 256>>>(edge_index);
    wprep_kernel<<<dim3(256, 3), 256>>>(lin_W, linl_W, linr_W);
    xsplit_kernel<<<20000, 256>>>(x);

    {
        dim3 grid(2, MTOT_ / 128);
        mma_gemm<<<grid, 256, SMEM_BYTES>>>(0, lin_b, nullptr);   // -> g_xl
    }
    gather_kernel<<<NN_, 256>>>(edge_attr, bond_W, bond_b, edge_weight, edge_index);
    {
        dim3 grid(2, MTOT_ / 128);
        mma_gemm<<<grid, 256, SMEM_BYTES>>>(1, linl_b, out);      // -> out
    }
}

// round 8
// speedup vs baseline: 2.0532x; 1.0282x over previous
#include <cuda_runtime.h>
#include <cuda_fp16.h>
#include <math.h>
#include <stdint.h>

// Problem constants
#define RC_    4        // R*CH
#define NN_    20000
#define EE_    100000
#define CC_    256
#define MTOT_  80000    // R*CH*N

// ---------------------------------------------------------------------------
// Scratch (static device globals; no runtime allocation)
// ---------------------------------------------------------------------------
__device__ __align__(256) float g_xl[MTOT_ * CC_];     // x @ lin_W + lin_b
__device__ int g_is64;

// CSR scratch
__device__ __align__(256) int g_icnt[NN_];             // zero-init; reset by scan
__device__ __align__(256) int g_rowstart[NN_ + 1];
__device__ __align__(256) int g_pos[NN_];
__device__ __align__(256) int g_ebkt[EE_];

// fp16 2-term split operands
__device__ __align__(256) __half g_xhi[MTOT_ * CC_];
__device__ __align__(256) __half g_xlo[MTOT_ * CC_];
__device__ __align__(256) __half g_ahi[MTOT_ * CC_];
__device__ __align__(256) __half g_alo[MTOT_ * CC_];
// Transposed fp16 weights, [n][k] layout
__device__ __align__(256) __half g_WT0[CC_ * CC_];  // lin_W
__device__ __align__(256) __half g_WT2[CC_ * CC_];  // linl_W
__device__ __align__(256) __half g_WT4[CC_ * CC_];  // linr_W

// ---------------------------------------------------------------------------
// PTX helpers (sm_80+ only)
// ---------------------------------------------------------------------------
__device__ __forceinline__ uint32_t smem_u32(const void* p) {
    uint32_t a;
    asm("{ .reg .u64 t; cvta.to.shared.u64 t, %1; cvt.u32.u64 %0, t; }"
        : "=r"(a) : "l"(p));
    return a;
}
__device__ __forceinline__ void cp16(uint32_t saddr, const void* g) {
    asm volatile("cp.async.cg.shared.global [%0], [%1], 16;"
                 :: "r"(saddr), "l"(g) : "memory");
}
#define CP_COMMIT() asm volatile("cp.async.commit_group;" ::: "memory")
#define CP_WAIT1()  asm volatile("cp.async.wait_group 1;" ::: "memory")
#define CP_WAIT0()  asm volatile("cp.async.wait_group 0;" ::: "memory")

#define LDSM4(r, addr) \
    asm volatile("ldmatrix.sync.aligned.m8n8.x4.shared.b16 {%0,%1,%2,%3}, [%4];" \
                 : "=r"((r)[0]), "=r"((r)[1]), "=r"((r)[2]), "=r"((r)[3]) \
                 : "r"(addr))

#define MMA16816(d, a, b0, b1) \
    asm volatile("mma.sync.aligned.m16n8k16.row.col.f32.f16.f16.f32 " \
                 "{%0,%1,%2,%3}, {%4,%5,%6,%7}, {%8,%9}, {%0,%1,%2,%3};" \
                 : "+f"((d)[0]), "+f"((d)[1]), "+f"((d)[2]), "+f"((d)[3]) \
                 : "r"((a)[0]), "r"((a)[1]), "r"((a)[2]), "r"((a)[3]), \
                   "r"(b0), "r"(b1))

// SMEM geometry: padded 80B row stride -> conflict-free ldmatrix
#define ROWB        80
#define TILE_BYTES  10240        // 128 rows * 80B
#define STAGE_BYTES 20480        // A tile + B tile
#define NSTAGE      3
#define SMEM_BYTES  61440        // 3 stages

// ---------------------------------------------------------------------------
// edge_index dtype detect + index load
// ---------------------------------------------------------------------------
__global__ void detect_kernel(const int* __restrict__ ei32) {
    __shared__ int any_nonzero;
    if (threadIdx.x == 0) any_nonzero = 0;
    __syncthreads();
    if (ei32[2 * threadIdx.x + 1] != 0) atomicOr(&any_nonzero, 1);
    __syncthreads();
    if (threadIdx.x == 0) g_is64 = (any_nonzero == 0) ? 1 : 0;
}
__device__ __forceinline__ int load_idx(const int* ei32, int pos) {
    int v = g_is64 ? ei32[2 * pos] : ei32[pos];
    return min(max(v, 0), NN_ - 1);
}

// ---------------------------------------------------------------------------
// CSR build: histogram -> scan (+ reset histogram) -> bucket fill
// ---------------------------------------------------------------------------
__global__ void icount_kernel(const int* __restrict__ ei32) {
    int e = blockIdx.x * 256 + threadIdx.x;
    if (e < EE_) atomicAdd(&g_icnt[load_idx(ei32, EE_ + e)], 1);
}

__global__ __launch_bounds__(1024) void scan_kernel() {
    __shared__ int buf[1024];
    __shared__ int carry;
    const int tid = threadIdx.x;
    if (tid == 0) carry = 0;
    __syncthreads();
    for (int chunk = 0; chunk < (NN_ + 1023) / 1024; chunk++) {
        int i = chunk * 1024 + tid;
        int v = (i < NN_) ? g_icnt[i] : 0;
        if (i < NN_) g_icnt[i] = 0;          // reset for next graph replay
        int add = carry;
        buf[tid] = v;
        __syncthreads();
        for (int off = 1; off < 1024; off <<= 1) {
            int t = (tid >= off) ? buf[tid - off] : 0;
            __syncthreads();
            buf[tid] += t;
            __syncthreads();
        }
        if (i < NN_) {
            int excl = add + buf[tid] - v;
            g_rowstart[i] = excl;
            g_pos[i] = excl;
        }
        __syncthreads();
        if (tid == 0) carry = add + buf[1023];
        __syncthreads();
    }
    if (tid == 0) g_rowstart[NN_] = carry;   // == EE_
}

__global__ void fill_kernel(const int* __restrict__ ei32) {
    int e = blockIdx.x * 256 + threadIdx.x;
    if (e < EE_) {
        int dst = load_idx(ei32, EE_ + e);
        int p = atomicAdd(&g_pos[dst], 1);
        g_ebkt[p] = e;
    }
}

// ---------------------------------------------------------------------------
// fp32 -> (hi,lo) fp16 split
// ---------------------------------------------------------------------------
__device__ __forceinline__ void split4(float4 v, __half2* H, __half2* L, size_t i4) {
    __half h0 = __float2half_rn(v.x);
    __half h1 = __float2half_rn(v.y);
    __half h2 = __float2half_rn(v.z);
    __half h3 = __float2half_rn(v.w);
    __half2 p;
    p.x = h0; p.y = h1; H[i4 * 2 + 0] = p;
    p.x = h2; p.y = h3; H[i4 * 2 + 1] = p;
    p.x = __float2half_rn(v.x - __half2float(h0));
    p.y = __float2half_rn(v.y - __half2float(h1));
    L[i4 * 2 + 0] = p;
    p.x = __float2half_rn(v.z - __half2float(h2));
    p.y = __float2half_rn(v.w - __half2float(h3));
    L[i4 * 2 + 1] = p;
}

__global__ void xsplit_kernel(const float* __restrict__ x) {
    size_t i4 = (size_t)blockIdx.x * 256 + threadIdx.x;
    float4 v = ((const float4*)x)[i4];
    split4(v, (__half2*)g_xhi, (__half2*)g_xlo, i4);
}

__global__ void wprep_kernel(const float* __restrict__ W0,
                             const float* __restrict__ W1,
                             const float* __restrict__ W2) {
    const float* W = (blockIdx.y == 0) ? W0 : ((blockIdx.y == 1) ? W1 : W2);
    __half* H = (blockIdx.y == 0) ? g_WT0 : ((blockIdx.y == 1) ? g_WT2 : g_WT4);
    int k = blockIdx.x, n = threadIdx.x;
    H[n * CC_ + k] = __float2half_rn(W[k * CC_ + n]);
}

// ---------------------------------------------------------------------------
// Fused message gather: block = dst node, thread = channel.
// ---------------------------------------------------------------------------
__global__ __launch_bounds__(256) void gather_kernel(
    const float* __restrict__ edge_attr,    // (E,16)
    const float* __restrict__ bond_W,       // (16,256)
    const float* __restrict__ bond_b,       // (256)
    const float* __restrict__ edge_weight,  // (RC, E)
    const int* __restrict__ ei32)
{
    const int n = blockIdx.x;
    const int c = threadIdx.x;

    float bw[16];
#pragma unroll
    for (int d = 0; d < 16; d++) bw[d] = bond_W[d * CC_ + c];
    const float bb = bond_b[c];

    const int s0 = g_rowstart[n];
    const int s1 = g_rowstart[n + 1];
    const int deg = s1 - s0;

    float acc0 = 0.f, acc1 = 0.f, acc2 = 0.f, acc3 = 0.f;

    for (int i = s0; i < s1; i++) {
        const int e = g_ebkt[i];
        const int src = load_idx(ei32, e);

        float emb = bb;
#pragma unroll
        for (int d = 0; d < 16; d++)
            emb = fmaf(__ldg(&edge_attr[e * 16 + d]), bw[d], emb);

        const float w0 = __ldg(&edge_weight[0 * EE_ + e]);
        const float w1 = __ldg(&edge_weight[1 * EE_ + e]);
        const float w2 = __ldg(&edge_weight[2 * EE_ + e]);
        const float w3 = __ldg(&edge_weight[3 * EE_ + e]);

        const float* xr = g_xl + (size_t)src * CC_ + c;
        const size_t rs = (size_t)NN_ * CC_;
        float v0 = xr[0 * rs] + emb;
        float v1 = xr[1 * rs] + emb;
        float v2 = xr[2 * rs] + emb;
        float v3 = xr[3 * rs] + emb;
        const float k = 0.70710678118654752f;
        acc0 += 0.5f * v0 * (1.0f + erff(v0 * k)) * w0;
        acc1 += 0.5f * v1 * (1.0f + erff(v1 * k)) * w1;
        acc2 += 0.5f * v2 * (1.0f + erff(v2 * k)) * w2;
        acc3 += 0.5f * v3 * (1.0f + erff(v3 * k)) * w3;
    }

    const float s = 1.0f / (float)max(deg, 1);
    float a[4] = {acc0 * s, acc1 * s, acc2 * s, acc3 * s};
#pragma unroll
    for (int rc = 0; rc < RC_; rc++) {
        size_t off = (size_t)(rc * NN_ + n) * CC_ + c;
        __half h = __float2half_rn(a[rc]);
        g_ahi[off] = h;
        g_alo[off] = __float2half_rn(a[rc] - __half2float(h));
    }
}

// ---------------------------------------------------------------------------
// fp16 mma.sync GEMM, 3-stage cp.async pipeline.
// CTA tile 128x128, BK=32, 8 warps (2M x 4N), warp tile 64x32.
// which==0: g_xl = [xhi,xlo] @ [W0,W0]^T + lin_b                 (K=512)
// which==1: out  = [ahi,alo,xhi,xlo] @ [W2,W2,W4,W4]^T + linl_b  (K=1024)
// ---------------------------------------------------------------------------
__device__ __forceinline__ void load_stage(char* smem, int s, int tid,
                                           const __half* Ag, const __half* Bg) {
    uint32_t a32 = smem_u32(smem + s * STAGE_BYTES);
    uint32_t b32 = a32 + TILE_BYTES;
#pragma unroll
    for (int i = 0; i < 2; i++) {
        int idx = tid + i * 256;       // 0..511
        int r = idx >> 2, ch = idx & 3;
        cp16(a32 + r * ROWB + ch * 16,
             (const char*)Ag + ((size_t)r * CC_ + ch * 8) * 2);
    }
#pragma unroll
    for (int i = 0; i < 2; i++) {
        int idx = tid + i * 256;
        int r = idx >> 2, ch = idx & 3;
        cp16(b32 + r * ROWB + ch * 16,
             (const char*)Bg + ((size_t)r * CC_ + ch * 8) * 2);
    }
}

__global__ __launch_bounds__(256, 2) void mma_gemm(
    int which, const float* __restrict__ bias, float* __restrict__ out_ext)
{
    extern __shared__ __align__(128) char smem[];
    const int tid = threadIdx.x, lane = tid & 31, wid = tid >> 5;
    const int warp_m = wid & 1, warp_n = wid >> 1;
    const int bx = blockIdx.x, by = blockIdx.y;
    const int g = lane >> 3, lr = lane & 7;

    const __half *Aseg[4], *Bseg[4];
    int nseg;
    float* outp;
    if (which == 0) {
        Aseg[0] = g_xhi; Aseg[1] = g_xlo;
        Bseg[0] = g_WT0; Bseg[1] = g_WT0;
        nseg = 2; outp = g_xl;
    } else {
        Aseg[0] = g_ahi; Aseg[1] = g_alo; Aseg[2] = g_xhi; Aseg[3] = g_xlo;
        Bseg[0] = g_WT2; Bseg[1] = g_WT2; Bseg[2] = g_WT4; Bseg[3] = g_WT4;
        nseg = 4; outp = out_ext;
    }
    const int NC = nseg * 8;    // BK=32 chunks per 256-K segment

    float acc[4][4][4];
#pragma unroll
    for (int mt = 0; mt < 4; mt++)
#pragma unroll
        for (int nt = 0; nt < 4; nt++)
#pragma unroll
            for (int q = 0; q < 4; q++) acc[mt][nt][q] = 0.f;

    const size_t arow = (size_t)by * 128 * CC_;
    const size_t brow = (size_t)bx * 128 * CC_;

    // Prologue: load chunks 0 and 1
    load_stage(smem, 0, tid, Aseg[0] + arow, Bseg[0] + brow);
    CP_COMMIT();
    {
        int seg = 1 >> 3, ko = (1 & 7) * 32;
        load_stage(smem, 1, tid, Aseg[seg] + arow + ko, Bseg[seg] + brow + ko);
        CP_COMMIT();
    }

    int buf = 0;
    for (int c = 0; c < NC; c++) {
        // Ensure chunk c's group has landed
        if (c + 1 < NC) { CP_WAIT1(); } else { CP_WAIT0(); }
        __syncthreads();   // all warps done with chunk c-1 (buffer (c+2)%3)

        // Prefetch chunk c+2 into the buffer last used by chunk c-1
        if (c + 2 < NC) {
            int seg = (c + 2) >> 3, ko = ((c + 2) & 7) * 32;
            int nb = (buf + 2 >= NSTAGE) ? buf + 2 - NSTAGE : buf + 2;
            load_stage(smem, nb, tid,
                       Aseg[seg] + arow + ko, Bseg[seg] + brow + ko);
            CP_COMMIT();
        }

        uint32_t a_base = smem_u32(smem + buf * STAGE_BYTES);
        uint32_t b_base = a_base + TILE_BYTES;
#pragma unroll
        for (int ks = 0; ks < 2; ks++) {
            uint32_t a[4][4];
#pragma unroll
            for (int mt = 0; mt < 4; mt++) {
                int row = warp_m * 64 + mt * 16 + (g & 1) * 8 + lr;
                LDSM4(a[mt], a_base + row * ROWB + ks * 32 + (g >> 1) * 16);
            }
            uint32_t b[2][4];
#pragma unroll
            for (int p = 0; p < 2; p++) {
                int row = warp_n * 32 + p * 16 + ((g >> 1) & 1) * 8 + lr;
                LDSM4(b[p], b_base + row * ROWB + ks * 32 + (g & 1) * 16);
            }
#pragma unroll
            for (int mt = 0; mt < 4; mt++)
#pragma unroll
                for (int nt = 0; nt < 4; nt++) {
                    int p = nt >> 1, h = (nt & 1) * 2;
                    MMA16816(acc[mt][nt], a[mt], b[p][h], b[p][h + 1]);
                }
        }
        buf = (buf + 1 >= NSTAGE) ? 0 : buf + 1;
    }

    const int tg = lane >> 2, tig = lane & 3;
#pragma unroll
    for (int mt = 0; mt < 4; mt++) {
#pragma unroll
        for (int nt = 0; nt < 4; nt++) {
            int row = by * 128 + warp_m * 64 + mt * 16 + tg;
            int col = bx * 128 + warp_n * 32 + nt * 8 + tig * 2;
            float b0 = bias[col], b1 = bias[col + 1];
            float2 v0, v1;
            v0.x = acc[mt][nt][0] + b0; v0.y = acc[mt][nt][1] + b1;
            v1.x = acc[mt][nt][2] + b0; v1.y = acc[mt][nt][3] + b1;
            *(float2*)(outp + (size_t)row * CC_ + col) = v0;
            *(float2*)(outp + (size_t)(row + 8) * CC_ + col) = v1;
        }
    }
}

// ---------------------------------------------------------------------------
extern "C" void kernel_launch(void* const* d_in, const int* in_sizes, int n_in,
                              void* d_out, int out_size) {
    const float* x           = (const float*)d_in[0];
    const float* edge_attr   = (const float*)d_in[1];
    const float* edge_weight = (const float*)d_in[2];
    const float* lin_W       = (const float*)d_in[3];
    const float* lin_b       = (const float*)d_in[4];
    const float* linl_W      = (const float*)d_in[5];
    const float* linl_b      = (const float*)d_in[6];
    const float* linr_W      = (const float*)d_in[7];
    const float* bond_W      = (const float*)d_in[8];
    const float* bond_b      = (const float*)d_in[9];
    const int*   edge_index  = (const int*)d_in[10];
    float*       out         = (float*)d_out;

    cudaFuncSetAttribute(mma_gemm, cudaFuncAttributeMaxDynamicSharedMemorySize,
                         SMEM_BYTES);

    detect_kernel<<<1, 256>>>(edge_index);
    icount_kernel<<<(EE_ + 255) / 256, 256>>>(edge_index);
    scan_kernel<<<1, 1024>>>();
    fill_kernel<<<(EE_ + 255) / 256, 256>>>(edge_index);
    wprep_kernel<<<dim3(256, 3), 256>>>(lin_W, linl_W, linr_W);
    xsplit_kernel<<<20000, 256>>>(x);

    {
        dim3 grid(2, MTOT_ / 128);
        mma_gemm<<<grid, 256, SMEM_BYTES>>>(0, lin_b, nullptr);   // -> g_xl
    }
    gather_kernel<<<NN_, 256>>>(edge_attr, bond_W, bond_b, edge_weight, edge_index);
    {
        dim3 grid(2, MTOT_ / 128);
        mma_gemm<<<grid, 256, SMEM_BYTES>>>(1, linl_b, out);      // -> out
    }
}